// round 12
// baseline (speedup 1.0000x reference)
#include <cuda_runtime.h>
#include <stdint.h>

// ChannelPair2D: out[p, k] = x[p, i_k] * x[p, j_k], (i,j) i<j row-major triu.
// C=64 -> 2016 pairs, 65536 pixels. HBM-write-bound (~504 MiB out).
//
// R10 = R8 (identity thread->quad mapping, contiguous 512B warp stores, outer
// unroll-1 pixel loop, short divergent arms) + register diet:
//   - meta table (uint32/thread) kept in regs; pair-index uint4 reloaded via
//     __ldg inside the boundary arm only (L1-resident) -> 4 fewer live regs
//   - __launch_bounds__(256, 8) -> <=32 regs -> 8 CTAs/SM.

#define C_CH  64
#define NPAIR 2016
#define NQ    504               // NPAIR/4 quads
#define TPB   256
#define PPB   8                 // pixels per block
#define PLANE (PPB * C_CH)      // floats per replica plane (512)

// ---------------- compile-time tables (IDENTITY order: slot q = quad q) -----
struct MetaTab  { unsigned v[2 * TPB]; };
struct PairTab  { uint4    v[2 * TPB]; };

constexpr int off_of(int i) { return i * (127 - i) / 2; }

constexpr MetaTab build_meta() {
    MetaTab t{};
    for (int s = 0; s < 2 * TPB; ++s) t.v[s] = 0u;
    for (int q = 0; q < NQ; ++q) {
        int k = 4 * q, i = 0;
        while (off_of(i + 1) <= k) ++i;
        int j = i + 1 + (k - off_of(i));
        if (j + 3 <= 63) {
            // fast: bit31 | xi float-idx [0:8) | shifted-vec float-idx [8:24)
            t.v[q] = 0x80000000u
                   | (unsigned)i
                   | ((unsigned)((j & 3) * PLANE + (j & ~3)) << 8);
        }
    }
    return t;
}

constexpr PairTab build_pairs() {
    PairTab t{};
    for (int s = 0; s < 2 * TPB; ++s) t.v[s] = uint4{0u, 0u, 0u, 0u};
    for (int q = 0; q < NQ; ++q) {
        int k = 4 * q, i = 0;
        while (off_of(i + 1) <= k) ++i;
        int j = i + 1 + (k - off_of(i));
        unsigned b[8] = {0,0,0,0,0,0,0,0};
        int ii = i, jj = j;
        for (int e = 0; e < 4; ++e) {
            b[2*e]   = (unsigned)ii;
            b[2*e+1] = (unsigned)jj;
            ++jj; if (jj > 63) { ++ii; jj = ii + 1; }
        }
        t.v[q].x = b[0] | (b[1] << 8) | (b[2] << 16) | (b[3] << 24);
        t.v[q].y = b[4] | (b[5] << 8) | (b[6] << 16) | (b[7] << 24);
    }
    return t;
}

__device__ const MetaTab g_meta  = build_meta();
__device__ const PairTab g_pairs = build_pairs();

// ---------------- kernel ----------------
__global__ __launch_bounds__(TPB, 8)
void channelpair_kernel(const float* __restrict__ x,
                        float* __restrict__ out,
                        int npix) {
    // Shifted replicas: plane s holds x_p[c+s]; fast path reads x[j..j+3] as
    // one aligned LDS.128 at plane j&3, col j&~3.
    __shared__ __align__(16) float Bf[4 * PLANE];   // 8 KB

    const int tid  = threadIdx.x;
    const int pix0 = blockIdx.x * PPB;

    // Thread's two quads: q0 = tid (always < NQ), q1 = tid + 256 (may be >= NQ).
    const unsigned m0 = g_meta.v[tid];
    const unsigned m1 = g_meta.v[tid + TPB];
    const bool     a1 = (tid + TPB) < NQ;

    // Plane 0: PPB*64 floats = 128 float4 loads (threads 0..127)
    if (tid < PPB * (C_CH / 4)) {
        const float4* src = (const float4*)(x + (size_t)pix0 * C_CH);
        const int pix = pix0 + tid / (C_CH / 4);
        ((float4*)Bf)[tid] = (pix < npix) ? src[tid] : make_float4(0.f, 0.f, 0.f, 0.f);
    }
    __syncthreads();

    // Replica planes 1..3 (conflict-free scalar copies, 6 per thread)
    for (int t = tid; t < 3 * PLANE; t += TPB) {
        const int r = t % PLANE;
        const int c = r & 63;
        int sc = c + (1 + t / PLANE);
        if (sc > 63) sc = 63;
        Bf[PLANE + t] = Bf[(r - c) + sc];
    }
    __syncthreads();

    // Decode once (register-resident; ~6 live regs total for both slots).
    const bool f0  = (m0 >> 31) != 0;
    const bool f1  = (m1 >> 31) != 0;
    const int  xi0 = (int)(m0 & 0xFFu);
    const int  sv0 = (int)((m0 >> 8) & 0xFFFFu);
    const int  xi1 = (int)(m1 & 0xFFu);
    const int  sv1 = (int)((m1 >> 8) & 0xFFFFu);

    float4* o0 = (float4*)out + (size_t)pix0 * NQ + tid;
    float4* o1 = o0 + TPB;

    const int rem = npix - pix0;
    const int pc  = rem >= PPB ? PPB : rem;

    // Outer pixel loop (proven geometry): whole block writes one pixel's
    // contiguous 8 KB per iteration; each warp's stores span contiguous 512B.
    #pragma unroll 1
    for (int p = 0; p < pc; ++p) {
        const int    off = p * C_CH;          // pixel offset within each plane
        const float* xv  = Bf + off;          // plane-0 view for this pixel

        // ---- quad q0 = tid ----
        {
            float4 r;
            if (f0) {
                const float  xi = xv[xi0];
                const float4 v  = *(const float4*)(Bf + sv0 + off);
                r.x = xi * v.x; r.y = xi * v.y; r.z = xi * v.z; r.w = xi * v.w;
            } else {
                const uint4 d = __ldg(&g_pairs.v[tid]);       // L1-resident
                const unsigned z = d.x, w = d.y;
                r.x = xv[z & 255u]         * xv[(z >> 8) & 255u];
                r.y = xv[(z >> 16) & 255u] * xv[z >> 24];
                r.z = xv[w & 255u]         * xv[(w >> 8) & 255u];
                r.w = xv[(w >> 16) & 255u] * xv[w >> 24];
            }
            o0[(size_t)p * NQ] = r;
        }
        // ---- quad q1 = tid + 256 ----
        if (a1) {
            float4 r;
            if (f1) {
                const float  xi = xv[xi1];
                const float4 v  = *(const float4*)(Bf + sv1 + off);
                r.x = xi * v.x; r.y = xi * v.y; r.z = xi * v.z; r.w = xi * v.w;
            } else {
                const uint4 d = __ldg(&g_pairs.v[tid + TPB]); // L1-resident
                const unsigned z = d.x, w = d.y;
                r.x = xv[z & 255u]         * xv[(z >> 8) & 255u];
                r.y = xv[(z >> 16) & 255u] * xv[z >> 24];
                r.z = xv[w & 255u]         * xv[(w >> 8) & 255u];
                r.w = xv[(w >> 16) & 255u] * xv[w >> 24];
            }
            o1[(size_t)p * NQ] = r;
        }
    }
}

extern "C" void kernel_launch(void* const* d_in, const int* in_sizes, int n_in,
                              void* d_out, int out_size) {
    const float* x = (const float*)d_in[0];
    float* out = (float*)d_out;

    const int npix = in_sizes[0] / C_CH;            // 65536
    const int nblk = (npix + PPB - 1) / PPB;        // 8192

    channelpair_kernel<<<nblk, TPB>>>(x, out, npix);
}